// round 4
// baseline (speedup 1.0000x reference)
#include <cuda_runtime.h>
#include <math.h>

#define DIM     768
#define NH      12
#define HD      64
#define HIDDEN  3072
#define SEQ     2048
#define BATCH   4
#define TOKENS  (BATCH*SEQ)   // 8192
#define EPS     1e-6f

// ---------------- scratch (static device globals; no allocations) -----------
__device__ float g_h    [(size_t)TOKENS * DIM];          //  25 MB  (LN output, reused)
__device__ float g_qkv  [(size_t)TOKENS * 3 * DIM];      //  75 MB
__device__ float g_scores[(size_t)BATCH * NH * SEQ * SEQ]; // 805 MB
__device__ float g_attn [(size_t)TOKENS * DIM];          //  25 MB
__device__ float g_x1   [(size_t)TOKENS * DIM];          //  25 MB
__device__ float g_h2   [(size_t)TOKENS * HIDDEN];       // 100 MB

// ---------------- LayerNorm: one block per token (768 = 256*3) --------------
__global__ void ln_kernel(const float* __restrict__ x, const float* __restrict__ g,
                          const float* __restrict__ b, float* __restrict__ out) {
    __shared__ float red[256];
    long t = blockIdx.x;
    const float* xr = x + t * DIM;
    int tid = threadIdx.x;
    float v0 = xr[tid], v1 = xr[tid + 256], v2 = xr[tid + 512];
    red[tid] = v0 + v1 + v2;
    __syncthreads();
    #pragma unroll
    for (int s = 128; s > 0; s >>= 1) { if (tid < s) red[tid] += red[tid + s]; __syncthreads(); }
    float mu = red[0] * (1.0f / DIM);
    __syncthreads();
    float d0 = v0 - mu, d1 = v1 - mu, d2 = v2 - mu;
    red[tid] = d0*d0 + d1*d1 + d2*d2;
    __syncthreads();
    #pragma unroll
    for (int s = 128; s > 0; s >>= 1) { if (tid < s) red[tid] += red[tid + s]; __syncthreads(); }
    float rinv = rsqrtf(red[0] * (1.0f / DIM) + EPS);
    float* orow = out + t * DIM;
    orow[tid]       = d0 * rinv * g[tid]       + b[tid];
    orow[tid + 256] = d1 * rinv * g[tid + 256] + b[tid + 256];
    orow[tid + 512] = d2 * rinv * g[tid + 512] + b[tid + 512];
}

// ---------------- Softmax: one block per score row (2048 = 256*8) -----------
__global__ void softmax_kernel(float* __restrict__ s) {
    __shared__ float red[256];
    float* p = s + (size_t)blockIdx.x * SEQ;
    int tid = threadIdx.x;
    float v[8];
    float m = -1e30f;
    #pragma unroll
    for (int i = 0; i < 8; i++) { v[i] = p[tid + i * 256]; m = fmaxf(m, v[i]); }
    red[tid] = m;
    __syncthreads();
    #pragma unroll
    for (int st = 128; st > 0; st >>= 1) { if (tid < st) red[tid] = fmaxf(red[tid], red[tid + st]); __syncthreads(); }
    m = red[0];
    __syncthreads();
    float sum = 0.f;
    #pragma unroll
    for (int i = 0; i < 8; i++) { v[i] = expf(v[i] - m); sum += v[i]; }
    red[tid] = sum;
    __syncthreads();
    #pragma unroll
    for (int st = 128; st > 0; st >>= 1) { if (tid < st) red[tid] += red[tid + st]; __syncthreads(); }
    float inv = 1.0f / red[0];
    #pragma unroll
    for (int i = 0; i < 8; i++) p[tid + i * 256] = v[i] * inv;
}

__device__ __forceinline__ float gelu_exact(float x) {
    return 0.5f * x * (1.0f + erff(x * 0.70710678118654752440f));
}

// ---------------- Generic SGEMM --------------------------------------------
// C[m,n] = scale * sum_k A[m,k] * Bop[n,k]  (+bias[n]) (gelu) (+res[m,n])
//   BT=true : B stored [N,K] (weight layout W[n,k]); BN must be 128
//   BT=false: B stored [K,N] (e.g. V tile);          BN must be 64
// A is always [M,K] K-major (lda). Batched over blockIdx.z via (b,h) strides.
// Requires: M%BM==0, N%BN==0, K%BK==0, lda/ldb multiples of 4, 16B alignment.
template<int BM, int BN, int BK, int TM, int TN, bool BT>
__global__ void __launch_bounds__(256, 2) gemm_kernel(
    const float* __restrict__ A, int lda, long sAb, long sAh,
    const float* __restrict__ B, int ldb, long sBb, long sBh,
    float* __restrict__ C, int ldc, long sCb, long sCh,
    const float* __restrict__ bias, const float* __restrict__ res,
    int K, float scale, int gelu)
{
    static_assert((BT && BN == 128) || (!BT && BN == 64), "cfg");
    __shared__ float As[BK][BM];
    __shared__ float Bs[BK][BN];

    int bh = blockIdx.z;
    int bb = bh / NH, hh = bh % NH;
    A += (long)bb * sAb + (long)hh * sAh;
    B += (long)bb * sBb + (long)hh * sBh;
    C += (long)bb * sCb + (long)hh * sCh;

    int tid  = threadIdx.x;
    int row0 = blockIdx.y * BM;
    int col0 = blockIdx.x * BN;

    // A tile load map: 128 rows x 8 k, one float4 per thread
    int arow = tid >> 1;
    int ak4  = (tid & 1) * 4;
    const float* Ag = A + (long)(row0 + arow) * lda + ak4;
    float4 aReg = *(const float4*)Ag;

    // B tile load map
    int brow = 0, bk4 = 0, bk = 0, bn2 = 0;
    const float* Bg;
    float4 bReg4 = make_float4(0, 0, 0, 0);
    float2 bReg2 = make_float2(0, 0);
    if constexpr (BT) {
        brow = tid >> 1; bk4 = (tid & 1) * 4;
        Bg = B + (long)(col0 + brow) * ldb + bk4;
        bReg4 = *(const float4*)Bg;
    } else {
        bk = tid >> 5; bn2 = (tid & 31) * 2;
        Bg = B + (long)bk * ldb + col0 + bn2;
        bReg2 = *(const float2*)Bg;
    }

    float acc[TM][TN];
    #pragma unroll
    for (int i = 0; i < TM; i++)
        #pragma unroll
        for (int j = 0; j < TN; j++) acc[i][j] = 0.f;

    int tx = tid % (BN / TN);
    int ty = tid / (BN / TN);

    for (int k0 = 0; k0 < K; k0 += BK) {
        // commit prefetched tile to smem (transposed A, B)
        As[ak4 + 0][arow] = aReg.x;
        As[ak4 + 1][arow] = aReg.y;
        As[ak4 + 2][arow] = aReg.z;
        As[ak4 + 3][arow] = aReg.w;
        if constexpr (BT) {
            Bs[bk4 + 0][brow] = bReg4.x;
            Bs[bk4 + 1][brow] = bReg4.y;
            Bs[bk4 + 2][brow] = bReg4.z;
            Bs[bk4 + 3][brow] = bReg4.w;
        } else {
            Bs[bk][bn2]     = bReg2.x;
            Bs[bk][bn2 + 1] = bReg2.y;
        }
        __syncthreads();

        // prefetch next tile (overlaps with compute below)
        if (k0 + BK < K) {
            aReg = *(const float4*)(Ag + (k0 + BK));
            if constexpr (BT) bReg4 = *(const float4*)(Bg + (k0 + BK));
            else              bReg2 = *(const float2*)(Bg + (long)(k0 + BK) * ldb);
        }

        #pragma unroll
        for (int kk = 0; kk < BK; kk++) {
            float a[TM], bv[TN];
            #pragma unroll
            for (int i = 0; i < TM; i += 4)
                *(float4*)&a[i] = *(const float4*)&As[kk][ty * TM + i];
            #pragma unroll
            for (int j = 0; j < TN; j += 4)
                *(float4*)&bv[j] = *(const float4*)&Bs[kk][tx * TN + j];
            #pragma unroll
            for (int i = 0; i < TM; i++)
                #pragma unroll
                for (int j = 0; j < TN; j++)
                    acc[i][j] = fmaf(a[i], bv[j], acc[i][j]);
        }
        __syncthreads();
    }

    // epilogue: scale, +bias, gelu, +residual, store (float4)
    #pragma unroll
    for (int i = 0; i < TM; i++) {
        int row = row0 + ty * TM + i;
        float* crow = C + (long)row * ldc;
        #pragma unroll
        for (int j = 0; j < TN; j += 4) {
            int col = col0 + tx * TN + j;
            float4 v;
            v.x = acc[i][j]     * scale;
            v.y = acc[i][j + 1] * scale;
            v.z = acc[i][j + 2] * scale;
            v.w = acc[i][j + 3] * scale;
            if (bias) {
                v.x += bias[col];     v.y += bias[col + 1];
                v.z += bias[col + 2]; v.w += bias[col + 3];
            }
            if (gelu) {
                v.x = gelu_exact(v.x); v.y = gelu_exact(v.y);
                v.z = gelu_exact(v.z); v.w = gelu_exact(v.w);
            }
            if (res) {
                float4 r = *(const float4*)&res[(long)row * ldc + col];
                v.x += r.x; v.y += r.y; v.z += r.z; v.w += r.w;
            }
            *(float4*)&crow[col] = v;
        }
    }
}

// ---------------- launch ----------------------------------------------------
extern "C" void kernel_launch(void* const* d_in, const int* in_sizes, int n_in,
                              void* d_out, int out_size) {
    const float* x      = (const float*)d_in[0];
    const float* ln1_g  = (const float*)d_in[1];
    const float* ln1_b  = (const float*)d_in[2];
    const float* qkv_w  = (const float*)d_in[3];
    const float* qkv_b  = (const float*)d_in[4];
    const float* proj_w = (const float*)d_in[5];
    const float* proj_b = (const float*)d_in[6];
    const float* ln2_g  = (const float*)d_in[7];
    const float* ln2_b  = (const float*)d_in[8];
    const float* fc1_w  = (const float*)d_in[9];
    const float* fc1_b  = (const float*)d_in[10];
    const float* fc2_w  = (const float*)d_in[11];
    const float* fc2_b  = (const float*)d_in[12];
    float* out = (float*)d_out;

    float *h, *qkv, *scores, *attn, *x1, *h2;
    cudaGetSymbolAddress((void**)&h,      g_h);
    cudaGetSymbolAddress((void**)&qkv,    g_qkv);
    cudaGetSymbolAddress((void**)&scores, g_scores);
    cudaGetSymbolAddress((void**)&attn,   g_attn);
    cudaGetSymbolAddress((void**)&x1,     g_x1);
    cudaGetSymbolAddress((void**)&h2,     g_h2);

    const long sQb = (long)SEQ * 3 * DIM;   // batch stride inside qkv
    const long sSh = (long)SEQ * SEQ;       // per-head score stride
    const long sSb = (long)NH * sSh;

    // 1. LN1
    ln_kernel<<<TOKENS, 256>>>(x, ln1_g, ln1_b, h);

    // 2. QKV = h @ qkv_w^T + qkv_b      [8192 x 2304], K=768
    gemm_kernel<128, 128, 8, 8, 8, true><<<dim3(3 * DIM / 128, TOKENS / 128, 1), 256>>>(
        h, DIM, 0, 0, qkv_w, DIM, 0, 0, qkv, 3 * DIM, 0, 0,
        qkv_b, nullptr, DIM, 1.0f, 0);

    // 3. scores = scale * Q @ K^T      batched [48] x [2048 x 2048], K=64
    gemm_kernel<128, 128, 8, 8, 8, true><<<dim3(SEQ / 128, SEQ / 128, BATCH * NH), 256>>>(
        qkv,        3 * DIM, sQb, HD,        // Q slice
        qkv + DIM,  3 * DIM, sQb, HD,        // K slice
        scores, SEQ, sSb, sSh,
        nullptr, nullptr, HD, 0.125f, 0);

    // 4. softmax over rows
    softmax_kernel<<<BATCH * NH * SEQ, 256>>>(scores);

    // 5. attn = P @ V                   batched [48] x [2048 x 64], K=2048
    gemm_kernel<128, 64, 8, 8, 4, false><<<dim3(1, SEQ / 128, BATCH * NH), 256>>>(
        scores, SEQ, sSb, sSh,
        qkv + 2 * DIM, 3 * DIM, sQb, HD,     // V slice, [K,N] layout
        attn, DIM, (long)SEQ * DIM, HD,
        nullptr, nullptr, SEQ, 1.0f, 0);

    // 6. x1 = x + attn @ proj_w^T + proj_b
    gemm_kernel<128, 128, 8, 8, 8, true><<<dim3(DIM / 128, TOKENS / 128, 1), 256>>>(
        attn, DIM, 0, 0, proj_w, DIM, 0, 0, x1, DIM, 0, 0,
        proj_b, x, DIM, 1.0f, 0);

    // 7. LN2
    ln_kernel<<<TOKENS, 256>>>(x1, ln2_g, ln2_b, h);

    // 8. h2 = gelu(h @ fc1_w^T + fc1_b)   [8192 x 3072], K=768
    gemm_kernel<128, 128, 8, 8, 8, true><<<dim3(HIDDEN / 128, TOKENS / 128, 1), 256>>>(
        h, DIM, 0, 0, fc1_w, DIM, 0, 0, h2, HIDDEN, 0, 0,
        fc1_b, nullptr, DIM, 1.0f, 1);

    // 9. out = x1 + h2 @ fc2_w^T + fc2_b  [8192 x 768], K=3072
    gemm_kernel<128, 128, 8, 8, 8, true><<<dim3(DIM / 128, TOKENS / 128, 1), 256>>>(
        h2, HIDDEN, 0, 0, fc2_w, HIDDEN, 0, 0, out, DIM, 0, 0,
        fc2_b, x1, HIDDEN, 1.0f, 0);
}

// round 5
// speedup vs baseline: 1.8654x; 1.8654x over previous
#include <cuda_runtime.h>
#include <math.h>
#include <stdint.h>

#define DIM     768
#define NH      12
#define HD      64
#define HIDDEN  3072
#define SEQ     2048
#define BATCH   4
#define TOKENS  (BATCH*SEQ)   // 8192
#define EPS     1e-6f

// ---------------- scratch (static device globals; no allocations) -----------
__device__ float g_h    [(size_t)TOKENS * DIM];
__device__ float g_qkv  [(size_t)TOKENS * 3 * DIM];
__device__ float g_scores[(size_t)BATCH * NH * SEQ * SEQ]; // 805 MB
__device__ float g_attn [(size_t)TOKENS * DIM];
__device__ float g_x1   [(size_t)TOKENS * DIM];
__device__ float g_h2   [(size_t)TOKENS * HIDDEN];

// ---------------- LayerNorm: one block per token (768 = 256*3) --------------
__global__ void ln_kernel(const float* __restrict__ x, const float* __restrict__ g,
                          const float* __restrict__ b, float* __restrict__ out) {
    __shared__ float red[256];
    long t = blockIdx.x;
    const float* xr = x + t * DIM;
    int tid = threadIdx.x;
    float v0 = xr[tid], v1 = xr[tid + 256], v2 = xr[tid + 512];
    red[tid] = v0 + v1 + v2;
    __syncthreads();
    #pragma unroll
    for (int s = 128; s > 0; s >>= 1) { if (tid < s) red[tid] += red[tid + s]; __syncthreads(); }
    float mu = red[0] * (1.0f / DIM);
    __syncthreads();
    float d0 = v0 - mu, d1 = v1 - mu, d2 = v2 - mu;
    red[tid] = d0*d0 + d1*d1 + d2*d2;
    __syncthreads();
    #pragma unroll
    for (int s = 128; s > 0; s >>= 1) { if (tid < s) red[tid] += red[tid + s]; __syncthreads(); }
    float rinv = rsqrtf(red[0] * (1.0f / DIM) + EPS);
    float* orow = out + t * DIM;
    orow[tid]       = d0 * rinv * g[tid]       + b[tid];
    orow[tid + 256] = d1 * rinv * g[tid + 256] + b[tid + 256];
    orow[tid + 512] = d2 * rinv * g[tid + 512] + b[tid + 512];
}

// ---------------- Softmax: one block per score row (2048 = 256*8) -----------
__global__ void softmax_kernel(float* __restrict__ s) {
    __shared__ float red[256];
    float* p = s + (size_t)blockIdx.x * SEQ;
    int tid = threadIdx.x;
    float v[8];
    float m = -1e30f;
    #pragma unroll
    for (int i = 0; i < 8; i++) { v[i] = p[tid + i * 256]; m = fmaxf(m, v[i]); }
    red[tid] = m;
    __syncthreads();
    #pragma unroll
    for (int st = 128; st > 0; st >>= 1) { if (tid < st) red[tid] = fmaxf(red[tid], red[tid + st]); __syncthreads(); }
    m = red[0];
    __syncthreads();
    float sum = 0.f;
    #pragma unroll
    for (int i = 0; i < 8; i++) { v[i] = expf(v[i] - m); sum += v[i]; }
    red[tid] = sum;
    __syncthreads();
    #pragma unroll
    for (int st = 128; st > 0; st >>= 1) { if (tid < st) red[tid] += red[tid + st]; __syncthreads(); }
    float inv = 1.0f / red[0];
    #pragma unroll
    for (int i = 0; i < 8; i++) p[tid + i * 256] = v[i] * inv;
}

__device__ __forceinline__ float gelu_exact(float x) {
    return 0.5f * x * (1.0f + erff(x * 0.70710678118654752440f));
}

__device__ __forceinline__ uint32_t f2tf(float f) {
    uint32_t u;
    asm("cvt.rna.tf32.f32 %0, %1;" : "=r"(u) : "f"(f));
    return u;
}

__device__ __forceinline__ void mma_tf32(float* c, const uint32_t* a, const uint32_t* b) {
    asm volatile(
        "mma.sync.aligned.m16n8k8.row.col.f32.tf32.tf32.f32 "
        "{%0,%1,%2,%3}, {%4,%5,%6,%7}, {%8,%9}, {%0,%1,%2,%3};"
        : "+f"(c[0]), "+f"(c[1]), "+f"(c[2]), "+f"(c[3])
        : "r"(a[0]), "r"(a[1]), "r"(a[2]), "r"(a[3]), "r"(b[0]), "r"(b[1]));
}

// ---------------- TF32 tensor-core GEMM -------------------------------------
// C[m,n] = scale * sum_k A[m,k] * Bop[n,k]  (+bias[n]) (gelu) (+res[m,n])
//   BT=true : B stored [N,K] (weight layout W[n,k]); BN = 128
//   BT=false: B stored [K,N] (V tile);               BN = 64
// A is [M,K] K-major. Batched over blockIdx.z via (b,h) strides.
// Tile: BM=128 x BN x BK=16. 256 threads = 4(m) x 2(n) warps.
// Warp tile: 32 x (BN/2)  ->  2 m16 tiles x (BN/16) n8 tiles.
// smem stored k-major with row stride == 8 (mod 32) floats -> conflict-free
// fragment loads (bank = 8*(lane&3) + lane>>2, all distinct).
template<int BN, bool BT>
__global__ void __launch_bounds__(256, 2) gemm_tf32_kernel(
    const float* __restrict__ A, int lda, long sAb, long sAh,
    const float* __restrict__ B, int ldb, long sBb, long sBh,
    float* __restrict__ C, int ldc, long sCb, long sCh,
    const float* __restrict__ bias, const float* __restrict__ res,
    int K, float scale, int gelu)
{
    constexpr int BM = 128, BK = 16;
    constexpr int WN = BN / 2;       // 64 or 32
    constexpr int NT = WN / 8;       // 8 or 4
    constexpr int MT = 2;            // WM = 32
    constexpr int ASTR = BM + 8;     // 136 : 136 % 32 == 8
    constexpr int BSTR = BN + 8;     // 136 or 72 : both == 8 (mod 32)

    __shared__ uint32_t As[BK][ASTR];
    __shared__ uint32_t Bs[BK][BSTR];

    int bh = blockIdx.z;
    int bb = bh / NH, hh = bh % NH;
    A += (long)bb * sAb + (long)hh * sAh;
    B += (long)bb * sBb + (long)hh * sBh;
    C += (long)bb * sCb + (long)hh * sCh;

    int tid    = threadIdx.x;
    int lane   = tid & 31;
    int warp   = tid >> 5;
    int warp_m = warp >> 1;          // 0..3
    int warp_n = warp & 1;           // 0..1
    int row0   = blockIdx.y * BM;
    int col0   = blockIdx.x * BN;

    // ---- global load maps (register prefetch) ----
    // A tile 128 x 16: thread -> row = tid>>1, k-half = (tid&1)*8, two float4s
    int arow = tid >> 1;
    int ak   = (tid & 1) * 8;
    const float* Ag = A + (long)(row0 + arow) * lda + ak;
    float4 aR0 = *(const float4*)Ag;
    float4 aR1 = *(const float4*)(Ag + 4);

    // B tile
    int brow = 0, bk = 0, bkr = 0, bn4 = 0;
    const float* Bg;
    float4 bR0 = make_float4(0,0,0,0), bR1 = make_float4(0,0,0,0);
    if constexpr (BT) {
        brow = tid >> 1; bk = (tid & 1) * 8;
        Bg = B + (long)(col0 + brow) * ldb + bk;
        bR0 = *(const float4*)Bg;
        bR1 = *(const float4*)(Bg + 4);
    } else {
        bkr = tid >> 4; bn4 = (tid & 15) * 4;      // 16 x 64 tile, 1 float4/thread
        Bg = B + (long)bkr * ldb + col0 + bn4;
        bR0 = *(const float4*)Bg;
    }

    float acc[MT][NT][4];
    #pragma unroll
    for (int mi = 0; mi < MT; mi++)
        #pragma unroll
        for (int ni = 0; ni < NT; ni++)
            #pragma unroll
            for (int r = 0; r < 4; r++) acc[mi][ni][r] = 0.f;

    for (int k0 = 0; k0 < K; k0 += BK) {
        // commit prefetched tile to smem (k-major, converted to tf32)
        As[ak + 0][arow] = f2tf(aR0.x);
        As[ak + 1][arow] = f2tf(aR0.y);
        As[ak + 2][arow] = f2tf(aR0.z);
        As[ak + 3][arow] = f2tf(aR0.w);
        As[ak + 4][arow] = f2tf(aR1.x);
        As[ak + 5][arow] = f2tf(aR1.y);
        As[ak + 6][arow] = f2tf(aR1.z);
        As[ak + 7][arow] = f2tf(aR1.w);
        if constexpr (BT) {
            Bs[bk + 0][brow] = f2tf(bR0.x);
            Bs[bk + 1][brow] = f2tf(bR0.y);
            Bs[bk + 2][brow] = f2tf(bR0.z);
            Bs[bk + 3][brow] = f2tf(bR0.w);
            Bs[bk + 4][brow] = f2tf(bR1.x);
            Bs[bk + 5][brow] = f2tf(bR1.y);
            Bs[bk + 6][brow] = f2tf(bR1.z);
            Bs[bk + 7][brow] = f2tf(bR1.w);
        } else {
            Bs[bkr][bn4 + 0] = f2tf(bR0.x);
            Bs[bkr][bn4 + 1] = f2tf(bR0.y);
            Bs[bkr][bn4 + 2] = f2tf(bR0.z);
            Bs[bkr][bn4 + 3] = f2tf(bR0.w);
        }
        __syncthreads();

        // prefetch next tile (overlaps with mma below)
        if (k0 + BK < K) {
            aR0 = *(const float4*)(Ag + (k0 + BK));
            aR1 = *(const float4*)(Ag + (k0 + BK) + 4);
            if constexpr (BT) {
                bR0 = *(const float4*)(Bg + (k0 + BK));
                bR1 = *(const float4*)(Bg + (k0 + BK) + 4);
            } else {
                bR0 = *(const float4*)(Bg + (long)(k0 + BK) * ldb);
            }
        }

        // two k=8 steps
        #pragma unroll
        for (int ks = 0; ks < 2; ks++) {
            int kb = ks * 8 + (lane & 3);
            uint32_t af[MT][4];
            #pragma unroll
            for (int mi = 0; mi < MT; mi++) {
                int r = warp_m * 32 + mi * 16 + (lane >> 2);
                af[mi][0] = As[kb][r];
                af[mi][1] = As[kb][r + 8];
                af[mi][2] = As[kb + 4][r];
                af[mi][3] = As[kb + 4][r + 8];
            }
            uint32_t bf[NT][2];
            #pragma unroll
            for (int ni = 0; ni < NT; ni++) {
                int c = warp_n * WN + ni * 8 + (lane >> 2);
                bf[ni][0] = Bs[kb][c];
                bf[ni][1] = Bs[kb + 4][c];
            }
            #pragma unroll
            for (int mi = 0; mi < MT; mi++)
                #pragma unroll
                for (int ni = 0; ni < NT; ni++)
                    mma_tf32(acc[mi][ni], af[mi], bf[ni]);
        }
        __syncthreads();
    }

    // ---- epilogue: scale, +bias, gelu, +residual, store float2 ----
    #pragma unroll
    for (int mi = 0; mi < MT; mi++) {
        #pragma unroll
        for (int half = 0; half < 2; half++) {
            int row = row0 + warp_m * 32 + mi * 16 + (lane >> 2) + half * 8;
            float* crow = C + (long)row * ldc;
            const float* rrow = res ? res + (long)row * ldc : (const float*)0;
            #pragma unroll
            for (int ni = 0; ni < NT; ni++) {
                int col = col0 + warp_n * WN + ni * 8 + (lane & 3) * 2;
                float v0 = acc[mi][ni][half * 2 + 0] * scale;
                float v1 = acc[mi][ni][half * 2 + 1] * scale;
                if (bias) { v0 += bias[col]; v1 += bias[col + 1]; }
                if (gelu) { v0 = gelu_exact(v0); v1 = gelu_exact(v1); }
                if (res)  { float2 rr = *(const float2*)&rrow[col]; v0 += rr.x; v1 += rr.y; }
                *(float2*)&crow[col] = make_float2(v0, v1);
            }
        }
    }
}

// ---------------- launch ----------------------------------------------------
extern "C" void kernel_launch(void* const* d_in, const int* in_sizes, int n_in,
                              void* d_out, int out_size) {
    const float* x      = (const float*)d_in[0];
    const float* ln1_g  = (const float*)d_in[1];
    const float* ln1_b  = (const float*)d_in[2];
    const float* qkv_w  = (const float*)d_in[3];
    const float* qkv_b  = (const float*)d_in[4];
    const float* proj_w = (const float*)d_in[5];
    const float* proj_b = (const float*)d_in[6];
    const float* ln2_g  = (const float*)d_in[7];
    const float* ln2_b  = (const float*)d_in[8];
    const float* fc1_w  = (const float*)d_in[9];
    const float* fc1_b  = (const float*)d_in[10];
    const float* fc2_w  = (const float*)d_in[11];
    const float* fc2_b  = (const float*)d_in[12];
    float* out = (float*)d_out;

    float *h, *qkv, *scores, *attn, *x1, *h2;
    cudaGetSymbolAddress((void**)&h,      g_h);
    cudaGetSymbolAddress((void**)&qkv,    g_qkv);
    cudaGetSymbolAddress((void**)&scores, g_scores);
    cudaGetSymbolAddress((void**)&attn,   g_attn);
    cudaGetSymbolAddress((void**)&x1,     g_x1);
    cudaGetSymbolAddress((void**)&h2,     g_h2);

    const long sQb = (long)SEQ * 3 * DIM;   // batch stride inside qkv
    const long sSh = (long)SEQ * SEQ;       // per-head score stride
    const long sSb = (long)NH * sSh;

    // 1. LN1
    ln_kernel<<<TOKENS, 256>>>(x, ln1_g, ln1_b, h);

    // 2. QKV = h @ qkv_w^T + qkv_b      [8192 x 2304], K=768
    gemm_tf32_kernel<128, true><<<dim3(3 * DIM / 128, TOKENS / 128, 1), 256>>>(
        h, DIM, 0, 0, qkv_w, DIM, 0, 0, qkv, 3 * DIM, 0, 0,
        qkv_b, nullptr, DIM, 1.0f, 0);

    // 3. scores = scale * Q @ K^T      batched [48] x [2048 x 2048], K=64
    gemm_tf32_kernel<128, true><<<dim3(SEQ / 128, SEQ / 128, BATCH * NH), 256>>>(
        qkv,        3 * DIM, sQb, HD,        // Q slice
        qkv + DIM,  3 * DIM, sQb, HD,        // K slice
        scores, SEQ, sSb, sSh,
        nullptr, nullptr, HD, 0.125f, 0);

    // 4. softmax over rows
    softmax_kernel<<<BATCH * NH * SEQ, 256>>>(scores);

    // 5. attn = P @ V                   batched [48] x [2048 x 64], K=2048
    gemm_tf32_kernel<64, false><<<dim3(1, SEQ / 128, BATCH * NH), 256>>>(
        scores, SEQ, sSb, sSh,
        qkv + 2 * DIM, 3 * DIM, sQb, HD,     // V slice, [K,N] layout
        attn, DIM, (long)SEQ * DIM, HD,
        nullptr, nullptr, SEQ, 1.0f, 0);

    // 6. x1 = x + attn @ proj_w^T + proj_b
    gemm_tf32_kernel<128, true><<<dim3(DIM / 128, TOKENS / 128, 1), 256>>>(
        attn, DIM, 0, 0, proj_w, DIM, 0, 0, x1, DIM, 0, 0,
        proj_b, x, DIM, 1.0f, 0);

    // 7. LN2
    ln_kernel<<<TOKENS, 256>>>(x1, ln2_g, ln2_b, h);

    // 8. h2 = gelu(h @ fc1_w^T + fc1_b)   [8192 x 3072], K=768
    gemm_tf32_kernel<128, true><<<dim3(HIDDEN / 128, TOKENS / 128, 1), 256>>>(
        h, DIM, 0, 0, fc1_w, DIM, 0, 0, h2, HIDDEN, 0, 0,
        fc1_b, nullptr, DIM, 1.0f, 1);

    // 9. out = x1 + h2 @ fc2_w^T + fc2_b  [8192 x 768], K=3072
    gemm_tf32_kernel<128, true><<<dim3(DIM / 128, TOKENS / 128, 1), 256>>>(
        h2, HIDDEN, 0, 0, fc2_w, HIDDEN, 0, 0, out, DIM, 0, 0,
        fc2_b, x1, HIDDEN, 1.0f, 0);
}

// round 6
// speedup vs baseline: 2.4880x; 1.3337x over previous
#include <cuda_runtime.h>
#include <math.h>
#include <stdint.h>

#define DIM     768
#define NH      12
#define HD      64
#define HIDDEN  3072
#define SEQ     2048
#define BATCH   4
#define TOKENS  (BATCH*SEQ)   // 8192
#define EPS     1e-6f

// ---------------- scratch (static device globals; no allocations) -----------
__device__ float g_h    [(size_t)TOKENS * DIM];
__device__ float g_qkv  [(size_t)TOKENS * 3 * DIM];
__device__ float g_attn [(size_t)TOKENS * DIM];
__device__ float g_x1   [(size_t)TOKENS * DIM];
__device__ float g_h2   [(size_t)TOKENS * HIDDEN];

// ---------------- LayerNorm: one block per token (768 = 256*3) --------------
__global__ void ln_kernel(const float* __restrict__ x, const float* __restrict__ g,
                          const float* __restrict__ b, float* __restrict__ out) {
    __shared__ float red[256];
    long t = blockIdx.x;
    const float* xr = x + t * DIM;
    int tid = threadIdx.x;
    float v0 = xr[tid], v1 = xr[tid + 256], v2 = xr[tid + 512];
    red[tid] = v0 + v1 + v2;
    __syncthreads();
    #pragma unroll
    for (int s = 128; s > 0; s >>= 1) { if (tid < s) red[tid] += red[tid + s]; __syncthreads(); }
    float mu = red[0] * (1.0f / DIM);
    __syncthreads();
    float d0 = v0 - mu, d1 = v1 - mu, d2 = v2 - mu;
    red[tid] = d0*d0 + d1*d1 + d2*d2;
    __syncthreads();
    #pragma unroll
    for (int s = 128; s > 0; s >>= 1) { if (tid < s) red[tid] += red[tid + s]; __syncthreads(); }
    float rinv = rsqrtf(red[0] * (1.0f / DIM) + EPS);
    float* orow = out + t * DIM;
    orow[tid]       = d0 * rinv * g[tid]       + b[tid];
    orow[tid + 256] = d1 * rinv * g[tid + 256] + b[tid + 256];
    orow[tid + 512] = d2 * rinv * g[tid + 512] + b[tid + 512];
}

__device__ __forceinline__ float gelu_exact(float x) {
    return 0.5f * x * (1.0f + erff(x * 0.70710678118654752440f));
}

__device__ __forceinline__ uint32_t f2tf(float f) {
    uint32_t u;
    asm("cvt.rna.tf32.f32 %0, %1;" : "=r"(u) : "f"(f));
    return u;
}

__device__ __forceinline__ void mma_tf32(float* c, const uint32_t* a, const uint32_t* b) {
    asm volatile(
        "mma.sync.aligned.m16n8k8.row.col.f32.tf32.tf32.f32 "
        "{%0,%1,%2,%3}, {%4,%5,%6,%7}, {%8,%9}, {%0,%1,%2,%3};"
        : "+f"(c[0]), "+f"(c[1]), "+f"(c[2]), "+f"(c[3])
        : "r"(a[0]), "r"(a[1]), "r"(a[2]), "r"(a[3]), "r"(b[0]), "r"(b[1]));
}

__device__ __forceinline__ void cp16(float* s, const float* g) {
    uint32_t sa = (uint32_t)__cvta_generic_to_shared(s);
    asm volatile("cp.async.cg.shared.global [%0], [%1], 16;" :: "r"(sa), "l"(g));
}

// ================== Flash attention ==========================================
// One block: 128 query rows of one (b,h). 256 threads = 8 warps, each warp owns
// a 16-row strip (row stats stay within a lane-quad -> shfl reductions only).
// K/V tiles 64x64 streamed with cp.async double buffering. S and O accumulate
// in tf32 mma fragments; P goes through smem (strides chosen so every fragment
// LDS pattern hits 32 distinct banks: 68=4, 72=8, 68=4 (mod 32)).
#define FA_BR   128
#define FA_BC   64
#define FA_NIT  (SEQ / FA_BC)          // 32
#define KS_STR  68                     // [n][k] rows, 64+4
#define VS_STR  72                     // [k][n] rows, 64+8
#define PS_STR  68                     // [m][k] rows, 64+4
#define KS_BUF  (FA_BC * KS_STR)
#define VS_BUF  (FA_BC * VS_STR)
#define FA_SMEM_FLOATS (2*KS_BUF + 2*VS_BUF + FA_BR*PS_STR)
#define FA_SMEM_BYTES  (FA_SMEM_FLOATS * 4)   // 106,496 B -> 2 CTAs/SM

extern __shared__ float fa_sm[];

__global__ void __launch_bounds__(256, 2) flash_kernel(
    const float* __restrict__ qkv, float* __restrict__ attn)
{
    float* Ks = fa_sm;                 // [2][FA_BC][KS_STR]
    float* Vs = Ks + 2 * KS_BUF;       // [2][FA_BC][VS_STR]
    float* Ps = Vs + 2 * VS_BUF;       // [FA_BR][PS_STR], also Q staging

    int tid  = threadIdx.x, lane = tid & 31, warp = tid >> 5;
    int r4 = lane >> 2, l4 = lane & 3;
    int bh = blockIdx.y, bb = bh / NH, hh = bh % NH;
    long base = (long)bb * SEQ * (3 * DIM) + hh * HD;
    const float* Qg = qkv + base + (long)blockIdx.x * FA_BR * (3 * DIM);
    const float* Kg = qkv + base + DIM;
    const float* Vg = qkv + base + 2 * DIM;

    // ---- stage Q tile [128][64] into Ps, then pin A-fragments in registers
    #pragma unroll
    for (int t = 0; t < 8; t++) {
        int id = tid + t * 256; int r = id >> 4, c = (id & 15) * 4;
        cp16(&Ps[r * PS_STR + c], Qg + (long)r * (3 * DIM) + c);
    }
    asm volatile("cp.async.commit_group;\n");
    asm volatile("cp.async.wait_group 0;\n" ::: "memory");
    __syncthreads();

    uint32_t qf[8][4];
    {
        int m0 = warp * 16 + r4;
        #pragma unroll
        for (int ks = 0; ks < 8; ks++) {
            int k0 = ks * 8 + l4;
            qf[ks][0] = __float_as_uint(Ps[m0 * PS_STR + k0]);
            qf[ks][1] = __float_as_uint(Ps[(m0 + 8) * PS_STR + k0]);
            qf[ks][2] = __float_as_uint(Ps[m0 * PS_STR + k0 + 4]);
            qf[ks][3] = __float_as_uint(Ps[(m0 + 8) * PS_STR + k0 + 4]);
        }
    }
    __syncthreads();

    // ---- preload K/V tile 0
    #pragma unroll
    for (int t = 0; t < 4; t++) {
        int id = tid + t * 256; int r = id >> 4, c = (id & 15) * 4;
        cp16(&Ks[r * KS_STR + c], Kg + (long)r * (3 * DIM) + c);
        cp16(&Vs[r * VS_STR + c], Vg + (long)r * (3 * DIM) + c);
    }
    asm volatile("cp.async.commit_group;\n");

    float accO[8][4];
    #pragma unroll
    for (int ni = 0; ni < 8; ni++)
        #pragma unroll
        for (int r = 0; r < 4; r++) accO[ni][r] = 0.f;
    float mrun[2] = {-INFINITY, -INFINITY};
    float lrun[2] = {0.f, 0.f};
    const float fscale = 0.125f * 1.44269504f;   // head scale * log2(e)

    for (int j = 0; j < FA_NIT; j++) {
        int buf = j & 1;
        float* Kb = Ks + buf * KS_BUF;
        float* Vb = Vs + buf * VS_BUF;

        asm volatile("cp.async.wait_group 0;\n" ::: "memory");
        __syncthreads();   // tile j visible; everyone done with iter j-1 smem

        if (j + 1 < FA_NIT) {
            int nb = (j + 1) & 1;
            const float* Kn = Kg + (long)(j + 1) * FA_BC * (3 * DIM);
            const float* Vn = Vg + (long)(j + 1) * FA_BC * (3 * DIM);
            #pragma unroll
            for (int t = 0; t < 4; t++) {
                int id = tid + t * 256; int r = id >> 4, c = (id & 15) * 4;
                cp16(&Ks[nb * KS_BUF + r * KS_STR + c], Kn + (long)r * (3 * DIM) + c);
                cp16(&Vs[nb * VS_BUF + r * VS_STR + c], Vn + (long)r * (3 * DIM) + c);
            }
            asm volatile("cp.async.commit_group;\n");
        }

        // ---- S = Q @ K^T (16 rows x 64 cols per warp)
        float accS[8][4];
        #pragma unroll
        for (int ni = 0; ni < 8; ni++)
            #pragma unroll
            for (int r = 0; r < 4; r++) accS[ni][r] = 0.f;
        #pragma unroll
        for (int ks = 0; ks < 8; ks++) {
            #pragma unroll
            for (int ni = 0; ni < 8; ni++) {
                int n = ni * 8 + r4, k = ks * 8 + l4;
                uint32_t bfr[2];
                bfr[0] = __float_as_uint(Kb[n * KS_STR + k]);
                bfr[1] = __float_as_uint(Kb[n * KS_STR + k + 4]);
                mma_tf32(accS[ni], qf[ks], bfr);
            }
        }
        #pragma unroll
        for (int ni = 0; ni < 8; ni++)
            #pragma unroll
            for (int r = 0; r < 4; r++) accS[ni][r] *= fscale;

        // ---- online softmax (rows r4 and r4+8 of this warp's strip)
        #pragma unroll
        for (int h = 0; h < 2; h++) {
            float tm = -INFINITY;
            #pragma unroll
            for (int ni = 0; ni < 8; ni++)
                tm = fmaxf(tm, fmaxf(accS[ni][2*h], accS[ni][2*h + 1]));
            tm = fmaxf(tm, __shfl_xor_sync(0xffffffffu, tm, 1));
            tm = fmaxf(tm, __shfl_xor_sync(0xffffffffu, tm, 2));
            float mn = fmaxf(mrun[h], tm);
            float alpha = exp2f(mrun[h] - mn);
            mrun[h] = mn;
            float ps = 0.f;
            int mrow = warp * 16 + r4 + 8 * h;
            #pragma unroll
            for (int ni = 0; ni < 8; ni++) {
                float p0 = exp2f(accS[ni][2*h]     - mn);
                float p1 = exp2f(accS[ni][2*h + 1] - mn);
                ps += p0 + p1;
                *(float2*)&Ps[mrow * PS_STR + ni * 8 + 2 * l4] = make_float2(p0, p1);
            }
            ps += __shfl_xor_sync(0xffffffffu, ps, 1);
            ps += __shfl_xor_sync(0xffffffffu, ps, 2);
            lrun[h] = lrun[h] * alpha + ps;
            #pragma unroll
            for (int ni = 0; ni < 8; ni++) {
                accO[ni][2*h]     *= alpha;
                accO[ni][2*h + 1] *= alpha;
            }
        }
        __syncthreads();   // P visible

        // ---- O += P @ V
        #pragma unroll
        for (int ks = 0; ks < 8; ks++) {
            uint32_t a[4];
            int m0 = warp * 16 + r4, kk = ks * 8 + l4;
            a[0] = __float_as_uint(Ps[m0 * PS_STR + kk]);
            a[1] = __float_as_uint(Ps[(m0 + 8) * PS_STR + kk]);
            a[2] = __float_as_uint(Ps[m0 * PS_STR + kk + 4]);
            a[3] = __float_as_uint(Ps[(m0 + 8) * PS_STR + kk + 4]);
            #pragma unroll
            for (int ni = 0; ni < 8; ni++) {
                uint32_t bfr[2];
                bfr[0] = __float_as_uint(Vb[(ks * 8 + l4)     * VS_STR + ni * 8 + r4]);
                bfr[1] = __float_as_uint(Vb[(ks * 8 + l4 + 4) * VS_STR + ni * 8 + r4]);
                mma_tf32(accO[ni], a, bfr);
            }
        }
    }

    // ---- epilogue: normalize, write [token][DIM] head slice
    float* orow_base = attn + ((long)bb * SEQ + (long)blockIdx.x * FA_BR) * DIM + hh * HD;
    #pragma unroll
    for (int h = 0; h < 2; h++) {
        float inv = 1.0f / lrun[h];
        int row = warp * 16 + r4 + 8 * h;
        float* orow = orow_base + (long)row * DIM;
        #pragma unroll
        for (int ni = 0; ni < 8; ni++) {
            *(float2*)&orow[ni * 8 + 2 * l4] =
                make_float2(accO[ni][2*h] * inv, accO[ni][2*h + 1] * inv);
        }
    }
}

// ---------------- TF32 tensor-core GEMM (unchanged from R4) -----------------
template<int BN, bool BT>
__global__ void __launch_bounds__(256, 2) gemm_tf32_kernel(
    const float* __restrict__ A, int lda, long sAb, long sAh,
    const float* __restrict__ B, int ldb, long sBb, long sBh,
    float* __restrict__ C, int ldc, long sCb, long sCh,
    const float* __restrict__ bias, const float* __restrict__ res,
    int K, float scale, int gelu)
{
    constexpr int BM = 128, BK = 16;
    constexpr int WN = BN / 2;
    constexpr int NT = WN / 8;
    constexpr int MT = 2;
    constexpr int ASTR = BM + 8;
    constexpr int BSTR = BN + 8;

    __shared__ uint32_t As[BK][ASTR];
    __shared__ uint32_t Bs[BK][BSTR];

    int bh = blockIdx.z;
    int bb = bh / NH, hh = bh % NH;
    A += (long)bb * sAb + (long)hh * sAh;
    B += (long)bb * sBb + (long)hh * sBh;
    C += (long)bb * sCb + (long)hh * sCh;

    int tid    = threadIdx.x;
    int lane   = tid & 31;
    int warp   = tid >> 5;
    int warp_m = warp >> 1;
    int warp_n = warp & 1;
    int row0   = blockIdx.y * BM;
    int col0   = blockIdx.x * BN;

    int arow = tid >> 1;
    int ak   = (tid & 1) * 8;
    const float* Ag = A + (long)(row0 + arow) * lda + ak;
    float4 aR0 = *(const float4*)Ag;
    float4 aR1 = *(const float4*)(Ag + 4);

    int brow = 0, bk = 0, bkr = 0, bn4 = 0;
    const float* Bg;
    float4 bR0 = make_float4(0,0,0,0), bR1 = make_float4(0,0,0,0);
    if constexpr (BT) {
        brow = tid >> 1; bk = (tid & 1) * 8;
        Bg = B + (long)(col0 + brow) * ldb + bk;
        bR0 = *(const float4*)Bg;
        bR1 = *(const float4*)(Bg + 4);
    } else {
        bkr = tid >> 4; bn4 = (tid & 15) * 4;
        Bg = B + (long)bkr * ldb + col0 + bn4;
        bR0 = *(const float4*)Bg;
    }

    float acc[MT][NT][4];
    #pragma unroll
    for (int mi = 0; mi < MT; mi++)
        #pragma unroll
        for (int ni = 0; ni < NT; ni++)
            #pragma unroll
            for (int r = 0; r < 4; r++) acc[mi][ni][r] = 0.f;

    for (int k0 = 0; k0 < K; k0 += BK) {
        As[ak + 0][arow] = f2tf(aR0.x);
        As[ak + 1][arow] = f2tf(aR0.y);
        As[ak + 2][arow] = f2tf(aR0.z);
        As[ak + 3][arow] = f2tf(aR0.w);
        As[ak + 4][arow] = f2tf(aR1.x);
        As[ak + 5][arow] = f2tf(aR1.y);
        As[ak + 6][arow] = f2tf(aR1.z);
        As[ak + 7][arow] = f2tf(aR1.w);
        if constexpr (BT) {
            Bs[bk + 0][brow] = f2tf(bR0.x);
            Bs[bk + 1][brow] = f2tf(bR0.y);
            Bs[bk + 2][brow] = f2tf(bR0.z);
            Bs[bk + 3][brow] = f2tf(bR0.w);
            Bs[bk + 4][brow] = f2tf(bR1.x);
            Bs[bk + 5][brow] = f2tf(bR1.y);
            Bs[bk + 6][brow] = f2tf(bR1.z);
            Bs[bk + 7][brow] = f2tf(bR1.w);
        } else {
            Bs[bkr][bn4 + 0] = f2tf(bR0.x);
            Bs[bkr][bn4 + 1] = f2tf(bR0.y);
            Bs[bkr][bn4 + 2] = f2tf(bR0.z);
            Bs[bkr][bn4 + 3] = f2tf(bR0.w);
        }
        __syncthreads();

        if (k0 + BK < K) {
            aR0 = *(const float4*)(Ag + (k0 + BK));
            aR1 = *(const float4*)(Ag + (k0 + BK) + 4);
            if constexpr (BT) {
                bR0 = *(const float4*)(Bg + (k0 + BK));
                bR1 = *(const float4*)(Bg + (k0 + BK) + 4);
            } else {
                bR0 = *(const float4*)(Bg + (long)(k0 + BK) * ldb);
            }
        }

        #pragma unroll
        for (int ks = 0; ks < 2; ks++) {
            int kb = ks * 8 + (lane & 3);
            uint32_t af[MT][4];
            #pragma unroll
            for (int mi = 0; mi < MT; mi++) {
                int r = warp_m * 32 + mi * 16 + (lane >> 2);
                af[mi][0] = As[kb][r];
                af[mi][1] = As[kb][r + 8];
                af[mi][2] = As[kb + 4][r];
                af[mi][3] = As[kb + 4][r + 8];
            }
            uint32_t bf[NT][2];
            #pragma unroll
            for (int ni = 0; ni < NT; ni++) {
                int c = warp_n * WN + ni * 8 + (lane >> 2);
                bf[ni][0] = Bs[kb][c];
                bf[ni][1] = Bs[kb + 4][c];
            }
            #pragma unroll
            for (int mi = 0; mi < MT; mi++)
                #pragma unroll
                for (int ni = 0; ni < NT; ni++)
                    mma_tf32(acc[mi][ni], af[mi], bf[ni]);
        }
        __syncthreads();
    }

    #pragma unroll
    for (int mi = 0; mi < MT; mi++) {
        #pragma unroll
        for (int half = 0; half < 2; half++) {
            int row = row0 + warp_m * 32 + mi * 16 + (lane >> 2) + half * 8;
            float* crow = C + (long)row * ldc;
            const float* rrow = res ? res + (long)row * ldc : (const float*)0;
            #pragma unroll
            for (int ni = 0; ni < NT; ni++) {
                int col = col0 + warp_n * WN + ni * 8 + (lane & 3) * 2;
                float v0 = acc[mi][ni][half * 2 + 0] * scale;
                float v1 = acc[mi][ni][half * 2 + 1] * scale;
                if (bias) { v0 += bias[col]; v1 += bias[col + 1]; }
                if (gelu) { v0 = gelu_exact(v0); v1 = gelu_exact(v1); }
                if (res)  { float2 rr = *(const float2*)&rrow[col]; v0 += rr.x; v1 += rr.y; }
                *(float2*)&crow[col] = make_float2(v0, v1);
            }
        }
    }
}

// ---------------- launch ----------------------------------------------------
extern "C" void kernel_launch(void* const* d_in, const int* in_sizes, int n_in,
                              void* d_out, int out_size) {
    const float* x      = (const float*)d_in[0];
    const float* ln1_g  = (const float*)d_in[1];
    const float* ln1_b  = (const float*)d_in[2];
    const float* qkv_w  = (const float*)d_in[3];
    const float* qkv_b  = (const float*)d_in[4];
    const float* proj_w = (const float*)d_in[5];
    const float* proj_b = (const float*)d_in[6];
    const float* ln2_g  = (const float*)d_in[7];
    const float* ln2_b  = (const float*)d_in[8];
    const float* fc1_w  = (const float*)d_in[9];
    const float* fc1_b  = (const float*)d_in[10];
    const float* fc2_w  = (const float*)d_in[11];
    const float* fc2_b  = (const float*)d_in[12];
    float* out = (float*)d_out;

    float *h, *qkv, *attn, *x1, *h2;
    cudaGetSymbolAddress((void**)&h,    g_h);
    cudaGetSymbolAddress((void**)&qkv,  g_qkv);
    cudaGetSymbolAddress((void**)&attn, g_attn);
    cudaGetSymbolAddress((void**)&x1,   g_x1);
    cudaGetSymbolAddress((void**)&h2,   g_h2);

    cudaFuncSetAttribute(flash_kernel,
                         cudaFuncAttributeMaxDynamicSharedMemorySize, FA_SMEM_BYTES);

    // 1. LN1
    ln_kernel<<<TOKENS, 256>>>(x, ln1_g, ln1_b, h);

    // 2. QKV = h @ qkv_w^T + qkv_b      [8192 x 2304], K=768
    gemm_tf32_kernel<128, true><<<dim3(3 * DIM / 128, TOKENS / 128, 1), 256>>>(
        h, DIM, 0, 0, qkv_w, DIM, 0, 0, qkv, 3 * DIM, 0, 0,
        qkv_b, nullptr, DIM, 1.0f, 0);

    // 3-5. fused flash attention -> attn [token][DIM]
    flash_kernel<<<dim3(SEQ / FA_BR, BATCH * NH), 256, FA_SMEM_BYTES>>>(qkv, attn);

    // 6. x1 = x + attn @ proj_w^T + proj_b
    gemm_tf32_kernel<128, true><<<dim3(DIM / 128, TOKENS / 128, 1), 256>>>(
        attn, DIM, 0, 0, proj_w, DIM, 0, 0, x1, DIM, 0, 0,
        proj_b, x, DIM, 1.0f, 0);

    // 7. LN2
    ln_kernel<<<TOKENS, 256>>>(x1, ln2_g, ln2_b, h);

    // 8. h2 = gelu(h @ fc1_w^T + fc1_b)   [8192 x 3072], K=768
    gemm_tf32_kernel<128, true><<<dim3(HIDDEN / 128, TOKENS / 128, 1), 256>>>(
        h, DIM, 0, 0, fc1_w, DIM, 0, 0, h2, HIDDEN, 0, 0,
        fc1_b, nullptr, DIM, 1.0f, 1);

    // 9. out = x1 + h2 @ fc2_w^T + fc2_b  [8192 x 768], K=3072
    gemm_tf32_kernel<128, true><<<dim3(DIM / 128, TOKENS / 128, 1), 256>>>(
        h2, HIDDEN, 0, 0, fc2_w, HIDDEN, 0, 0, out, DIM, 0, 0,
        fc2_b, x1, HIDDEN, 1.0f, 0);
}

// round 7
// speedup vs baseline: 3.6983x; 1.4865x over previous
#include <cuda_runtime.h>
#include <math.h>
#include <stdint.h>

#define DIM     768
#define NH      12
#define HD      64
#define HIDDEN  3072
#define SEQ     2048
#define BATCH   4
#define TOKENS  (BATCH*SEQ)   // 8192
#define EPS     1e-6f

// ---------------- scratch (static device globals; no allocations) -----------
__device__ float g_h    [(size_t)TOKENS * DIM];
__device__ float g_qkv  [(size_t)TOKENS * 3 * DIM];
__device__ float g_attn [(size_t)TOKENS * DIM];
__device__ float g_x1   [(size_t)TOKENS * DIM];
__device__ float g_h2   [(size_t)TOKENS * HIDDEN];

extern __shared__ float dynsm[];

__device__ __forceinline__ float gelu_exact(float x) {
    return 0.5f * x * (1.0f + erff(x * 0.70710678118654752440f));
}

__device__ __forceinline__ float ex2a(float x) {
    float y;
    asm("ex2.approx.ftz.f32 %0, %1;" : "=f"(y) : "f"(x));
    return y;
}

__device__ __forceinline__ void mma_tf32(float* c, const uint32_t* a, const uint32_t* b) {
    asm volatile(
        "mma.sync.aligned.m16n8k8.row.col.f32.tf32.tf32.f32 "
        "{%0,%1,%2,%3}, {%4,%5,%6,%7}, {%8,%9}, {%0,%1,%2,%3};"
        : "+f"(c[0]), "+f"(c[1]), "+f"(c[2]), "+f"(c[3])
        : "r"(a[0]), "r"(a[1]), "r"(a[2]), "r"(a[3]), "r"(b[0]), "r"(b[1]));
}

__device__ __forceinline__ void cp16(float* s, const float* g) {
    uint32_t sa = (uint32_t)__cvta_generic_to_shared(s);
    asm volatile("cp.async.cg.shared.global [%0], [%1], 16;" :: "r"(sa), "l"(g));
}

// ---------------- LayerNorm: one warp per token ------------------------------
__global__ void ln_kernel(const float* __restrict__ x, const float* __restrict__ g,
                          const float* __restrict__ b, float* __restrict__ out) {
    int lane = threadIdx.x & 31, warp = threadIdx.x >> 5;
    long t = (long)blockIdx.x * 8 + warp;
    const float* xr = x + t * DIM;
    float4 v[6];
    float s = 0.f;
    #pragma unroll
    for (int i = 0; i < 6; i++) {
        v[i] = *(const float4*)&xr[(i * 32 + lane) * 4];
        s += v[i].x + v[i].y + v[i].z + v[i].w;
    }
    #pragma unroll
    for (int o = 16; o; o >>= 1) s += __shfl_xor_sync(0xffffffffu, s, o);
    float mu = s * (1.0f / DIM);
    float q = 0.f;
    #pragma unroll
    for (int i = 0; i < 6; i++) {
        v[i].x -= mu; v[i].y -= mu; v[i].z -= mu; v[i].w -= mu;
        q += v[i].x*v[i].x + v[i].y*v[i].y + v[i].z*v[i].z + v[i].w*v[i].w;
    }
    #pragma unroll
    for (int o = 16; o; o >>= 1) q += __shfl_xor_sync(0xffffffffu, q, o);
    float rinv = rsqrtf(q * (1.0f / DIM) + EPS);
    float* orow = out + t * DIM;
    #pragma unroll
    for (int i = 0; i < 6; i++) {
        int idx = (i * 32 + lane) * 4;
        float4 gg = *(const float4*)&g[idx];
        float4 bb = *(const float4*)&b[idx];
        float4 o4;
        o4.x = v[i].x * rinv * gg.x + bb.x;
        o4.y = v[i].y * rinv * gg.y + bb.y;
        o4.z = v[i].z * rinv * gg.z + bb.z;
        o4.w = v[i].w * rinv * gg.w + bb.w;
        *(float4*)&orow[idx] = o4;
    }
}

// ================== Flash attention ==========================================
#define FA_BR   128
#define FA_BC   64
#define FA_NIT  (SEQ / FA_BC)          // 32
#define KS_STR  68
#define VS_STR  72
#define PS_STR  68
#define KS_BUF  (FA_BC * KS_STR)
#define VS_BUF  (FA_BC * VS_STR)
#define FA_SMEM_FLOATS (2*KS_BUF + 2*VS_BUF + FA_BR*PS_STR)
#define FA_SMEM_BYTES  (FA_SMEM_FLOATS * 4)   // 106,496 B -> 2 CTAs/SM

__global__ void __launch_bounds__(256, 2) flash_kernel(
    const float* __restrict__ qkv, float* __restrict__ attn)
{
    float* Ks = dynsm;
    float* Vs = Ks + 2 * KS_BUF;
    float* Ps = Vs + 2 * VS_BUF;

    int tid  = threadIdx.x, lane = tid & 31, warp = tid >> 5;
    int r4 = lane >> 2, l4 = lane & 3;
    int bh = blockIdx.y, bb = bh / NH, hh = bh % NH;
    long base = (long)bb * SEQ * (3 * DIM) + hh * HD;
    const float* Qg = qkv + base + (long)blockIdx.x * FA_BR * (3 * DIM);
    const float* Kg = qkv + base + DIM;
    const float* Vg = qkv + base + 2 * DIM;

    // stage Q tile [128][64] into Ps, pin A-fragments in registers
    #pragma unroll
    for (int t = 0; t < 8; t++) {
        int id = tid + t * 256; int r = id >> 4, c = (id & 15) * 4;
        cp16(&Ps[r * PS_STR + c], Qg + (long)r * (3 * DIM) + c);
    }
    asm volatile("cp.async.commit_group;\n");
    asm volatile("cp.async.wait_group 0;\n" ::: "memory");
    __syncthreads();

    uint32_t qf[8][4];
    {
        int m0 = warp * 16 + r4;
        #pragma unroll
        for (int ks = 0; ks < 8; ks++) {
            int k0 = ks * 8 + l4;
            qf[ks][0] = __float_as_uint(Ps[m0 * PS_STR + k0]);
            qf[ks][1] = __float_as_uint(Ps[(m0 + 8) * PS_STR + k0]);
            qf[ks][2] = __float_as_uint(Ps[m0 * PS_STR + k0 + 4]);
            qf[ks][3] = __float_as_uint(Ps[(m0 + 8) * PS_STR + k0 + 4]);
        }
    }
    __syncthreads();

    // preload K/V tile 0
    #pragma unroll
    for (int t = 0; t < 4; t++) {
        int id = tid + t * 256; int r = id >> 4, c = (id & 15) * 4;
        cp16(&Ks[r * KS_STR + c], Kg + (long)r * (3 * DIM) + c);
        cp16(&Vs[r * VS_STR + c], Vg + (long)r * (3 * DIM) + c);
    }
    asm volatile("cp.async.commit_group;\n");

    float accO[8][4];
    #pragma unroll
    for (int ni = 0; ni < 8; ni++)
        #pragma unroll
        for (int r = 0; r < 4; r++) accO[ni][r] = 0.f;
    float mrun[2] = {-INFINITY, -INFINITY};
    float lrun[2] = {0.f, 0.f};
    const float fscale = 0.125f * 1.44269504f;

    for (int j = 0; j < FA_NIT; j++) {
        int buf = j & 1;
        float* Kb = Ks + buf * KS_BUF;
        float* Vb = Vs + buf * VS_BUF;

        asm volatile("cp.async.wait_group 0;\n" ::: "memory");
        __syncthreads();

        if (j + 1 < FA_NIT) {
            int nb = (j + 1) & 1;
            const float* Kn = Kg + (long)(j + 1) * FA_BC * (3 * DIM);
            const float* Vn = Vg + (long)(j + 1) * FA_BC * (3 * DIM);
            #pragma unroll
            for (int t = 0; t < 4; t++) {
                int id = tid + t * 256; int r = id >> 4, c = (id & 15) * 4;
                cp16(&Ks[nb * KS_BUF + r * KS_STR + c], Kn + (long)r * (3 * DIM) + c);
                cp16(&Vs[nb * VS_BUF + r * VS_STR + c], Vn + (long)r * (3 * DIM) + c);
            }
            asm volatile("cp.async.commit_group;\n");
        }

        // S = Q @ K^T
        float accS[8][4];
        #pragma unroll
        for (int ni = 0; ni < 8; ni++)
            #pragma unroll
            for (int r = 0; r < 4; r++) accS[ni][r] = 0.f;
        #pragma unroll
        for (int ks = 0; ks < 8; ks++) {
            #pragma unroll
            for (int ni = 0; ni < 8; ni++) {
                int n = ni * 8 + r4, k = ks * 8 + l4;
                uint32_t bfr[2];
                bfr[0] = __float_as_uint(Kb[n * KS_STR + k]);
                bfr[1] = __float_as_uint(Kb[n * KS_STR + k + 4]);
                mma_tf32(accS[ni], qf[ks], bfr);
            }
        }
        #pragma unroll
        for (int ni = 0; ni < 8; ni++)
            #pragma unroll
            for (int r = 0; r < 4; r++) accS[ni][r] *= fscale;

        // online softmax
        #pragma unroll
        for (int h = 0; h < 2; h++) {
            float tm = -INFINITY;
            #pragma unroll
            for (int ni = 0; ni < 8; ni++)
                tm = fmaxf(tm, fmaxf(accS[ni][2*h], accS[ni][2*h + 1]));
            tm = fmaxf(tm, __shfl_xor_sync(0xffffffffu, tm, 1));
            tm = fmaxf(tm, __shfl_xor_sync(0xffffffffu, tm, 2));
            float mn = fmaxf(mrun[h], tm);
            float alpha = ex2a(mrun[h] - mn);
            mrun[h] = mn;
            float ps = 0.f;
            int mrow = warp * 16 + r4 + 8 * h;
            #pragma unroll
            for (int ni = 0; ni < 8; ni++) {
                float p0 = ex2a(accS[ni][2*h]     - mn);
                float p1 = ex2a(accS[ni][2*h + 1] - mn);
                ps += p0 + p1;
                *(float2*)&Ps[mrow * PS_STR + ni * 8 + 2 * l4] = make_float2(p0, p1);
            }
            ps += __shfl_xor_sync(0xffffffffu, ps, 1);
            ps += __shfl_xor_sync(0xffffffffu, ps, 2);
            lrun[h] = lrun[h] * alpha + ps;
            #pragma unroll
            for (int ni = 0; ni < 8; ni++) {
                accO[ni][2*h]     *= alpha;
                accO[ni][2*h + 1] *= alpha;
            }
        }
        __syncthreads();

        // O += P @ V
        #pragma unroll
        for (int ks = 0; ks < 8; ks++) {
            uint32_t a[4];
            int m0 = warp * 16 + r4, kk = ks * 8 + l4;
            a[0] = __float_as_uint(Ps[m0 * PS_STR + kk]);
            a[1] = __float_as_uint(Ps[(m0 + 8) * PS_STR + kk]);
            a[2] = __float_as_uint(Ps[m0 * PS_STR + kk + 4]);
            a[3] = __float_as_uint(Ps[(m0 + 8) * PS_STR + kk + 4]);
            #pragma unroll
            for (int ni = 0; ni < 8; ni++) {
                uint32_t bfr[2];
                bfr[0] = __float_as_uint(Vb[(ks * 8 + l4)     * VS_STR + ni * 8 + r4]);
                bfr[1] = __float_as_uint(Vb[(ks * 8 + l4 + 4) * VS_STR + ni * 8 + r4]);
                mma_tf32(accO[ni], a, bfr);
            }
        }
    }

    float* orow_base = attn + ((long)bb * SEQ + (long)blockIdx.x * FA_BR) * DIM + hh * HD;
    #pragma unroll
    for (int h = 0; h < 2; h++) {
        float inv = 1.0f / lrun[h];
        int row = warp * 16 + r4 + 8 * h;
        float* orow = orow_base + (long)row * DIM;
        #pragma unroll
        for (int ni = 0; ni < 8; ni++) {
            *(float2*)&orow[ni * 8 + 2 * l4] =
                make_float2(accO[ni][2*h] * inv, accO[ni][2*h + 1] * inv);
        }
    }
}

// ---------------- TF32 GEMM: cp.async 2-stage pipeline ----------------------
// C[m,n] = sum_k A[m,k] * B[n,k]  (+bias[n]) (gelu) (+res[m,n])
// Tile 128x128xBK32, 256 threads = 4(m) x 2(n) warps, warp 32x64.
// smem [m][k] row-major, stride 36 (4*r4+l4 mod 32 -> conflict-free frag LDS).
// One __syncthreads per K-tile; loads for j+1 overlap mma of j.
#define GM_STR   36
#define GM_BK    32
#define GM_STAGE (128 * GM_STR)                 // floats per operand per stage
#define GM_SMEM_BYTES (4 * GM_STAGE * 4)        // 2 ops x 2 stages = 73,728 B

__global__ void __launch_bounds__(256, 2) gemm_tf32_kernel(
    const float* __restrict__ A, int lda,
    const float* __restrict__ B, int ldb,
    float* __restrict__ C, int ldc,
    const float* __restrict__ bias, const float* __restrict__ res,
    int K, int gelu)
{
    float* As = dynsm;                 // [2][128][GM_STR]
    float* Bs = dynsm + 2 * GM_STAGE;  // [2][128][GM_STR]

    int tid    = threadIdx.x;
    int lane   = tid & 31;
    int warp   = tid >> 5;
    int warp_m = warp >> 1;            // 0..3
    int warp_n = warp & 1;             // 0..1
    int r4 = lane >> 2, l4 = lane & 3;
    int row0   = blockIdx.y * 128;
    int col0   = blockIdx.x * 128;

    const float* Ab = A + (long)row0 * lda;
    const float* Bb = B + (long)col0 * ldb;

    int nt = K / GM_BK;

    // per-thread load map: 4 chunks of 16B for each operand
    int lrow[4], lc4[4];
    #pragma unroll
    for (int t = 0; t < 4; t++) {
        int c = tid + t * 256;
        lrow[t] = c >> 3;
        lc4[t]  = (c & 7) * 4;
    }

    // prologue: stage 0
    #pragma unroll
    for (int t = 0; t < 4; t++) {
        cp16(&As[lrow[t] * GM_STR + lc4[t]], Ab + (long)lrow[t] * lda + lc4[t]);
        cp16(&Bs[lrow[t] * GM_STR + lc4[t]], Bb + (long)lrow[t] * ldb + lc4[t]);
    }
    asm volatile("cp.async.commit_group;\n");

    float acc[2][8][4];
    #pragma unroll
    for (int mi = 0; mi < 2; mi++)
        #pragma unroll
        for (int ni = 0; ni < 8; ni++)
            #pragma unroll
            for (int r = 0; r < 4; r++) acc[mi][ni][r] = 0.f;

    for (int j = 0; j < nt; j++) {
        asm volatile("cp.async.wait_group 0;\n" ::: "memory");
        __syncthreads();

        if (j + 1 < nt) {
            int nb = (j + 1) & 1;
            int k0 = (j + 1) * GM_BK;
            #pragma unroll
            for (int t = 0; t < 4; t++) {
                cp16(&As[(nb * 128 + lrow[t]) * GM_STR + lc4[t]],
                     Ab + (long)lrow[t] * lda + k0 + lc4[t]);
                cp16(&Bs[(nb * 128 + lrow[t]) * GM_STR + lc4[t]],
                     Bb + (long)lrow[t] * ldb + k0 + lc4[t]);
            }
            asm volatile("cp.async.commit_group;\n");
        }

        const float* Asb = As + (j & 1) * GM_STAGE;
        const float* Bsb = Bs + (j & 1) * GM_STAGE;

        #pragma unroll
        for (int ks = 0; ks < 4; ks++) {
            int kb = ks * 8 + l4;
            uint32_t af[2][4];
            #pragma unroll
            for (int mi = 0; mi < 2; mi++) {
                int r = warp_m * 32 + mi * 16 + r4;
                af[mi][0] = __float_as_uint(Asb[r * GM_STR + kb]);
                af[mi][1] = __float_as_uint(Asb[(r + 8) * GM_STR + kb]);
                af[mi][2] = __float_as_uint(Asb[r * GM_STR + kb + 4]);
                af[mi][3] = __float_as_uint(Asb[(r + 8) * GM_STR + kb + 4]);
            }
            uint32_t bf[8][2];
            #pragma unroll
            for (int ni = 0; ni < 8; ni++) {
                int c = warp_n * 64 + ni * 8 + r4;
                bf[ni][0] = __float_as_uint(Bsb[c * GM_STR + kb]);
                bf[ni][1] = __float_as_uint(Bsb[c * GM_STR + kb + 4]);
            }
            #pragma unroll
            for (int mi = 0; mi < 2; mi++)
                #pragma unroll
                for (int ni = 0; ni < 8; ni++)
                    mma_tf32(acc[mi][ni], af[mi], bf[ni]);
        }
    }

    // epilogue
    #pragma unroll
    for (int mi = 0; mi < 2; mi++) {
        #pragma unroll
        for (int half = 0; half < 2; half++) {
            int row = row0 + warp_m * 32 + mi * 16 + r4 + half * 8;
            float* crow = C + (long)row * ldc;
            const float* rrow = res ? res + (long)row * ldc : (const float*)0;
            #pragma unroll
            for (int ni = 0; ni < 8; ni++) {
                int col = col0 + warp_n * 64 + ni * 8 + l4 * 2;
                float v0 = acc[mi][ni][half * 2 + 0];
                float v1 = acc[mi][ni][half * 2 + 1];
                if (bias) { v0 += bias[col]; v1 += bias[col + 1]; }
                if (gelu) { v0 = gelu_exact(v0); v1 = gelu_exact(v1); }
                if (res)  { float2 rr = *(const float2*)&rrow[col]; v0 += rr.x; v1 += rr.y; }
                *(float2*)&crow[col] = make_float2(v0, v1);
            }
        }
    }
}

// ---------------- launch ----------------------------------------------------
extern "C" void kernel_launch(void* const* d_in, const int* in_sizes, int n_in,
                              void* d_out, int out_size) {
    const float* x      = (const float*)d_in[0];
    const float* ln1_g  = (const float*)d_in[1];
    const float* ln1_b  = (const float*)d_in[2];
    const float* qkv_w  = (const float*)d_in[3];
    const float* qkv_b  = (const float*)d_in[4];
    const float* proj_w = (const float*)d_in[5];
    const float* proj_b = (const float*)d_in[6];
    const float* ln2_g  = (const float*)d_in[7];
    const float* ln2_b  = (const float*)d_in[8];
    const float* fc1_w  = (const float*)d_in[9];
    const float* fc1_b  = (const float*)d_in[10];
    const float* fc2_w  = (const float*)d_in[11];
    const float* fc2_b  = (const float*)d_in[12];
    float* out = (float*)d_out;

    float *h, *qkv, *attn, *x1, *h2;
    cudaGetSymbolAddress((void**)&h,    g_h);
    cudaGetSymbolAddress((void**)&qkv,  g_qkv);
    cudaGetSymbolAddress((void**)&attn, g_attn);
    cudaGetSymbolAddress((void**)&x1,   g_x1);
    cudaGetSymbolAddress((void**)&h2,   g_h2);

    cudaFuncSetAttribute(flash_kernel,
                         cudaFuncAttributeMaxDynamicSharedMemorySize, FA_SMEM_BYTES);
    cudaFuncSetAttribute(gemm_tf32_kernel,
                         cudaFuncAttributeMaxDynamicSharedMemorySize, GM_SMEM_BYTES);

    // 1. LN1
    ln_kernel<<<TOKENS / 8, 256>>>(x, ln1_g, ln1_b, h);

    // 2. QKV = h @ qkv_w^T + qkv_b      [8192 x 2304], K=768
    gemm_tf32_kernel<<<dim3(3 * DIM / 128, TOKENS / 128), 256, GM_SMEM_BYTES>>>(
        h, DIM, qkv_w, DIM, qkv, 3 * DIM, qkv_b, nullptr, DIM, 0);

    // 3-5. fused flash attention -> attn [token][DIM]
    flash_kernel<<<dim3(SEQ / FA_BR, BATCH * NH), 256, FA_SMEM_BYTES>>>(qkv, attn);

    // 6. x1 = x + attn @ proj_w^T + proj_b
    gemm_tf32_kernel<<<dim3(DIM / 128, TOKENS / 128), 256, GM_SMEM_BYTES>>>(
        attn, DIM, proj_w, DIM, x1, DIM, proj_b, x, DIM, 0);

    // 7. LN2
    ln_kernel<<<TOKENS / 8, 256>>>(x1, ln2_g, ln2_b, h);

    // 8. h2 = gelu(h @ fc1_w^T + fc1_b)   [8192 x 3072], K=768
    gemm_tf32_kernel<<<dim3(HIDDEN / 128, TOKENS / 128), 256, GM_SMEM_BYTES>>>(
        h, DIM, fc1_w, DIM, h2, HIDDEN, fc1_b, nullptr, DIM, 1);

    // 9. out = x1 + h2 @ fc2_w^T + fc2_b  [8192 x 768], K=3072
    gemm_tf32_kernel<<<dim3(DIM / 128, TOKENS / 128), 256, GM_SMEM_BYTES>>>(
        h2, HIDDEN, fc2_w, HIDDEN, out, DIM, fc2_b, x1, HIDDEN, 0);
}

// round 8
// speedup vs baseline: 3.8351x; 1.0370x over previous
#include <cuda_runtime.h>
#include <math.h>
#include <stdint.h>

#define DIM     768
#define NH      12
#define HD      64
#define HIDDEN  3072
#define SEQ     2048
#define BATCH   4
#define TOKENS  (BATCH*SEQ)   // 8192
#define EPS     1e-6f

// ---------------- scratch (static device globals; no allocations) -----------
__device__ float g_h    [(size_t)TOKENS * DIM];
__device__ float g_qkv  [(size_t)TOKENS * 3 * DIM];
__device__ float g_attn [(size_t)TOKENS * DIM];
__device__ float g_x1   [(size_t)TOKENS * DIM];
__device__ float g_h2   [(size_t)TOKENS * HIDDEN];

extern __shared__ float dynsm[];

__device__ __forceinline__ float gelu_exact(float x) {
    return 0.5f * x * (1.0f + erff(x * 0.70710678118654752440f));
}

__device__ __forceinline__ float ex2a(float x) {
    float y;
    asm("ex2.approx.ftz.f32 %0, %1;" : "=f"(y) : "f"(x));
    return y;
}

__device__ __forceinline__ void mma_tf32(float* c, const uint32_t* a, const uint32_t* b) {
    asm volatile(
        "mma.sync.aligned.m16n8k8.row.col.f32.tf32.tf32.f32 "
        "{%0,%1,%2,%3}, {%4,%5,%6,%7}, {%8,%9}, {%0,%1,%2,%3};"
        : "+f"(c[0]), "+f"(c[1]), "+f"(c[2]), "+f"(c[3])
        : "r"(a[0]), "r"(a[1]), "r"(a[2]), "r"(a[3]), "r"(b[0]), "r"(b[1]));
}

__device__ __forceinline__ void cp16(float* s, const float* g) {
    uint32_t sa = (uint32_t)__cvta_generic_to_shared(s);
    asm volatile("cp.async.cg.shared.global [%0], [%1], 16;" :: "r"(sa), "l"(g));
}

// ---------------- LayerNorm: one warp per token ------------------------------
__global__ void ln_kernel(const float* __restrict__ x, const float* __restrict__ g,
                          const float* __restrict__ b, float* __restrict__ out) {
    int lane = threadIdx.x & 31, warp = threadIdx.x >> 5;
    long t = (long)blockIdx.x * 8 + warp;
    const float* xr = x + t * DIM;
    float4 v[6];
    float s = 0.f;
    #pragma unroll
    for (int i = 0; i < 6; i++) {
        v[i] = *(const float4*)&xr[(i * 32 + lane) * 4];
        s += v[i].x + v[i].y + v[i].z + v[i].w;
    }
    #pragma unroll
    for (int o = 16; o; o >>= 1) s += __shfl_xor_sync(0xffffffffu, s, o);
    float mu = s * (1.0f / DIM);
    float q = 0.f;
    #pragma unroll
    for (int i = 0; i < 6; i++) {
        v[i].x -= mu; v[i].y -= mu; v[i].z -= mu; v[i].w -= mu;
        q += v[i].x*v[i].x + v[i].y*v[i].y + v[i].z*v[i].z + v[i].w*v[i].w;
    }
    #pragma unroll
    for (int o = 16; o; o >>= 1) q += __shfl_xor_sync(0xffffffffu, q, o);
    float rinv = rsqrtf(q * (1.0f / DIM) + EPS);
    float* orow = out + t * DIM;
    #pragma unroll
    for (int i = 0; i < 6; i++) {
        int idx = (i * 32 + lane) * 4;
        float4 gg = *(const float4*)&g[idx];
        float4 bb = *(const float4*)&b[idx];
        float4 o4;
        o4.x = v[i].x * rinv * gg.x + bb.x;
        o4.y = v[i].y * rinv * gg.y + bb.y;
        o4.z = v[i].z * rinv * gg.z + bb.z;
        o4.w = v[i].w * rinv * gg.w + bb.w;
        *(float4*)&orow[idx] = o4;
    }
}

// ================== Flash attention ==========================================
// 128 query rows per CTA, 8 warps x 16-row strips. Q lives in smem (staged
// once); K/V 64x64 tiles double-buffered via cp.async. P NEVER touches smem:
// the QK C-fragment is reused as the PV A-fragment via register renaming
// {c0,c2,c1,c3}, with V rows permuted by pi=[0,2,4,6,1,3,5,7] within each
// 8-row group at load time (free: index math in the cp.async source).
// One __syncthreads per KV tile.
#define FA_BR   128
#define FA_BC   64
#define FA_NIT  (SEQ / FA_BC)          // 32
#define QS_STR  68
#define KS_STR  68
#define VS_STR  72
#define KS_BUF  (FA_BC * KS_STR)
#define VS_BUF  (FA_BC * VS_STR)
#define FA_SMEM_FLOATS (FA_BR*QS_STR + 2*KS_BUF + 2*VS_BUF)
#define FA_SMEM_BYTES  (FA_SMEM_FLOATS * 4)   // 106,496 B -> 2 CTAs/SM

__global__ void __launch_bounds__(256, 2) flash_kernel(
    const float* __restrict__ qkv, float* __restrict__ attn)
{
    float* Qs = dynsm;                     // [128][QS_STR]
    float* Ks = Qs + FA_BR * QS_STR;       // [2][64][KS_STR]
    float* Vs = Ks + 2 * KS_BUF;           // [2][64][VS_STR] (pi-permuted rows)

    int tid  = threadIdx.x, lane = tid & 31, warp = tid >> 5;
    int r4 = lane >> 2, l4 = lane & 3;
    int bh = blockIdx.y, bb = bh / NH, hh = bh % NH;
    long base = (long)bb * SEQ * (3 * DIM) + hh * HD;
    const float* Qg = qkv + base + (long)blockIdx.x * FA_BR * (3 * DIM);
    const float* Kg = qkv + base + DIM;
    const float* Vg = qkv + base + 2 * DIM;

    // stage Q tile [128][64]
    #pragma unroll
    for (int t = 0; t < 8; t++) {
        int id = tid + t * 256; int r = id >> 4, c = (id & 15) * 4;
        cp16(&Qs[r * QS_STR + c], Qg + (long)r * (3 * DIM) + c);
    }
    asm volatile("cp.async.commit_group;\n");

    // preload K/V tile 0 (V rows permuted)
    #pragma unroll
    for (int t = 0; t < 4; t++) {
        int id = tid + t * 256; int r = id >> 4, c = (id & 15) * 4;
        int rv = (r & ~7) | (((r & 3) << 1) | ((r >> 2) & 1));
        cp16(&Ks[r * KS_STR + c], Kg + (long)r * (3 * DIM) + c);
        cp16(&Vs[r * VS_STR + c], Vg + (long)rv * (3 * DIM) + c);
    }
    asm volatile("cp.async.commit_group;\n");

    float accO[8][4];
    #pragma unroll
    for (int ni = 0; ni < 8; ni++)
        #pragma unroll
        for (int r = 0; r < 4; r++) accO[ni][r] = 0.f;
    float mrun[2] = {-INFINITY, -INFINITY};
    float lrun[2] = {0.f, 0.f};
    const float fscale = 0.125f * 1.44269504f;
    int m0 = warp * 16 + r4;

    for (int j = 0; j < FA_NIT; j++) {
        float* Kb = Ks + (j & 1) * KS_BUF;
        float* Vb = Vs + (j & 1) * VS_BUF;

        asm volatile("cp.async.wait_group 0;\n" ::: "memory");
        __syncthreads();   // tile j visible; all warps done with buffer j-1

        if (j + 1 < FA_NIT) {
            int nb = (j + 1) & 1;
            const float* Kn = Kg + (long)(j + 1) * FA_BC * (3 * DIM);
            const float* Vn = Vg + (long)(j + 1) * FA_BC * (3 * DIM);
            #pragma unroll
            for (int t = 0; t < 4; t++) {
                int id = tid + t * 256; int r = id >> 4, c = (id & 15) * 4;
                int rv = (r & ~7) | (((r & 3) << 1) | ((r >> 2) & 1));
                cp16(&Ks[nb * KS_BUF + r * KS_STR + c], Kn + (long)r * (3 * DIM) + c);
                cp16(&Vs[nb * VS_BUF + r * VS_STR + c], Vn + (long)rv * (3 * DIM) + c);
            }
            asm volatile("cp.async.commit_group;\n");
        }

        // ---- S = Q @ K^T (Q fragments from smem)
        float accS[8][4];
        #pragma unroll
        for (int ni = 0; ni < 8; ni++)
            #pragma unroll
            for (int r = 0; r < 4; r++) accS[ni][r] = 0.f;
        #pragma unroll
        for (int ks = 0; ks < 8; ks++) {
            int kb = ks * 8 + l4;
            uint32_t af[4];
            af[0] = __float_as_uint(Qs[m0 * QS_STR + kb]);
            af[1] = __float_as_uint(Qs[(m0 + 8) * QS_STR + kb]);
            af[2] = __float_as_uint(Qs[m0 * QS_STR + kb + 4]);
            af[3] = __float_as_uint(Qs[(m0 + 8) * QS_STR + kb + 4]);
            #pragma unroll
            for (int ni = 0; ni < 8; ni++) {
                int n = ni * 8 + r4;
                uint32_t bfr[2];
                bfr[0] = __float_as_uint(Kb[n * KS_STR + kb]);
                bfr[1] = __float_as_uint(Kb[n * KS_STR + kb + 4]);
                mma_tf32(accS[ni], af, bfr);
            }
        }
        #pragma unroll
        for (int ni = 0; ni < 8; ni++)
            #pragma unroll
            for (int r = 0; r < 4; r++) accS[ni][r] *= fscale;

        // ---- online softmax; p written back into accS (stays in registers)
        #pragma unroll
        for (int h = 0; h < 2; h++) {
            float tm = -INFINITY;
            #pragma unroll
            for (int ni = 0; ni < 8; ni++)
                tm = fmaxf(tm, fmaxf(accS[ni][2*h], accS[ni][2*h + 1]));
            tm = fmaxf(tm, __shfl_xor_sync(0xffffffffu, tm, 1));
            tm = fmaxf(tm, __shfl_xor_sync(0xffffffffu, tm, 2));
            float mn = fmaxf(mrun[h], tm);
            float alpha = ex2a(mrun[h] - mn);
            mrun[h] = mn;
            float ps = 0.f;
            #pragma unroll
            for (int ni = 0; ni < 8; ni++) {
                float p0 = ex2a(accS[ni][2*h]     - mn);
                float p1 = ex2a(accS[ni][2*h + 1] - mn);
                ps += p0 + p1;
                accS[ni][2*h] = p0; accS[ni][2*h + 1] = p1;
            }
            ps += __shfl_xor_sync(0xffffffffu, ps, 1);
            ps += __shfl_xor_sync(0xffffffffu, ps, 2);
            lrun[h] = lrun[h] * alpha + ps;
            #pragma unroll
            for (int ni = 0; ni < 8; ni++) {
                accO[ni][2*h]     *= alpha;
                accO[ni][2*h + 1] *= alpha;
            }
        }

        // ---- O += P @ V  (A-fragment = renamed C-fragment; V rows permuted)
        #pragma unroll
        for (int ks = 0; ks < 8; ks++) {
            uint32_t a[4];
            a[0] = __float_as_uint(accS[ks][0]);
            a[1] = __float_as_uint(accS[ks][2]);
            a[2] = __float_as_uint(accS[ks][1]);
            a[3] = __float_as_uint(accS[ks][3]);
            #pragma unroll
            for (int ni = 0; ni < 8; ni++) {
                uint32_t bfr[2];
                bfr[0] = __float_as_uint(Vb[(ks * 8 + l4)     * VS_STR + ni * 8 + r4]);
                bfr[1] = __float_as_uint(Vb[(ks * 8 + l4 + 4) * VS_STR + ni * 8 + r4]);
                mma_tf32(accO[ni], a, bfr);
            }
        }
    }

    float* orow_base = attn + ((long)bb * SEQ + (long)blockIdx.x * FA_BR) * DIM + hh * HD;
    #pragma unroll
    for (int h = 0; h < 2; h++) {
        float inv = 1.0f / lrun[h];
        int row = warp * 16 + r4 + 8 * h;
        float* orow = orow_base + (long)row * DIM;
        #pragma unroll
        for (int ni = 0; ni < 8; ni++) {
            *(float2*)&orow[ni * 8 + 2 * l4] =
                make_float2(accO[ni][2*h] * inv, accO[ni][2*h + 1] * inv);
        }
    }
}

// ---------------- TF32 GEMM: cp.async 3-stage pipeline ----------------------
// C[m,n] = sum_k A[m,k] * B[n,k]  (+bias[n]) (gelu) (+res[m,n])
// Tile 128x128xBK32, 256 threads = 4(m) x 2(n) warps, warp 32x64.
// smem [m][k] row-major, stride 36 (conflict-free fragment LDS).
// 3 stages, wait_group 1: loads span two compute tiles.
#define GM_STR   36
#define GM_BK    32
#define GM_STAGE (128 * GM_STR)                 // floats per operand per stage
#define GM_SMEM_BYTES (6 * GM_STAGE * 4)        // 2 ops x 3 stages = 110,592 B

__global__ void __launch_bounds__(256, 2) gemm_tf32_kernel(
    const float* __restrict__ A, int lda,
    const float* __restrict__ B, int ldb,
    float* __restrict__ C, int ldc,
    const float* __restrict__ bias, const float* __restrict__ res,
    int K, int gelu)
{
    float* As = dynsm;                 // [3][128][GM_STR]
    float* Bs = dynsm + 3 * GM_STAGE;  // [3][128][GM_STR]

    int tid    = threadIdx.x;
    int lane   = tid & 31;
    int warp   = tid >> 5;
    int warp_m = warp >> 1;
    int warp_n = warp & 1;
    int r4 = lane >> 2, l4 = lane & 3;
    int row0   = blockIdx.y * 128;
    int col0   = blockIdx.x * 128;

    const float* Ab = A + (long)row0 * lda;
    const float* Bb = B + (long)col0 * ldb;

    int nt = K / GM_BK;

    int lrow[4], lc4[4];
    #pragma unroll
    for (int t = 0; t < 4; t++) {
        int c = tid + t * 256;
        lrow[t] = c >> 3;
        lc4[t]  = (c & 7) * 4;
    }

    // prologue: stages 0 and 1 (tiles 0, 1); nt >= 2 always here
    #pragma unroll
    for (int t = 0; t < 4; t++) {
        cp16(&As[lrow[t] * GM_STR + lc4[t]], Ab + (long)lrow[t] * lda + lc4[t]);
        cp16(&Bs[lrow[t] * GM_STR + lc4[t]], Bb + (long)lrow[t] * ldb + lc4[t]);
    }
    asm volatile("cp.async.commit_group;\n");
    #pragma unroll
    for (int t = 0; t < 4; t++) {
        cp16(&As[(128 + lrow[t]) * GM_STR + lc4[t]], Ab + (long)lrow[t] * lda + GM_BK + lc4[t]);
        cp16(&Bs[(128 + lrow[t]) * GM_STR + lc4[t]], Bb + (long)lrow[t] * ldb + GM_BK + lc4[t]);
    }
    asm volatile("cp.async.commit_group;\n");

    float acc[2][8][4];
    #pragma unroll
    for (int mi = 0; mi < 2; mi++)
        #pragma unroll
        for (int ni = 0; ni < 8; ni++)
            #pragma unroll
            for (int r = 0; r < 4; r++) acc[mi][ni][r] = 0.f;

    int stage = 0, nstage = 2;
    for (int j = 0; j < nt; j++) {
        if (j + 1 < nt) asm volatile("cp.async.wait_group 1;\n" ::: "memory");
        else            asm volatile("cp.async.wait_group 0;\n" ::: "memory");
        __syncthreads();

        if (j + 2 < nt) {
            int k0 = (j + 2) * GM_BK;
            #pragma unroll
            for (int t = 0; t < 4; t++) {
                cp16(&As[(nstage * 128 + lrow[t]) * GM_STR + lc4[t]],
                     Ab + (long)lrow[t] * lda + k0 + lc4[t]);
                cp16(&Bs[(nstage * 128 + lrow[t]) * GM_STR + lc4[t]],
                     Bb + (long)lrow[t] * ldb + k0 + lc4[t]);
            }
            asm volatile("cp.async.commit_group;\n");
        }
        nstage = nstage + 1 == 3 ? 0 : nstage + 1;

        const float* Asb = As + stage * GM_STAGE;
        const float* Bsb = Bs + stage * GM_STAGE;
        stage = stage + 1 == 3 ? 0 : stage + 1;

        #pragma unroll
        for (int ks = 0; ks < 4; ks++) {
            int kb = ks * 8 + l4;
            uint32_t af[2][4];
            #pragma unroll
            for (int mi = 0; mi < 2; mi++) {
                int r = warp_m * 32 + mi * 16 + r4;
                af[mi][0] = __float_as_uint(Asb[r * GM_STR + kb]);
                af[mi][1] = __float_as_uint(Asb[(r + 8) * GM_STR + kb]);
                af[mi][2] = __float_as_uint(Asb[r * GM_STR + kb + 4]);
                af[mi][3] = __float_as_uint(Asb[(r + 8) * GM_STR + kb + 4]);
            }
            uint32_t bf[8][2];
            #pragma unroll
            for (int ni = 0; ni < 8; ni++) {
                int c = warp_n * 64 + ni * 8 + r4;
                bf[ni][0] = __float_as_uint(Bsb[c * GM_STR + kb]);
                bf[ni][1] = __float_as_uint(Bsb[c * GM_STR + kb + 4]);
            }
            #pragma unroll
            for (int mi = 0; mi < 2; mi++)
                #pragma unroll
                for (int ni = 0; ni < 8; ni++)
                    mma_tf32(acc[mi][ni], af[mi], bf[ni]);
        }
    }

    // epilogue
    #pragma unroll
    for (int mi = 0; mi < 2; mi++) {
        #pragma unroll
        for (int half = 0; half < 2; half++) {
            int row = row0 + warp_m * 32 + mi * 16 + r4 + half * 8;
            float* crow = C + (long)row * ldc;
            const float* rrow = res ? res + (long)row * ldc : (const float*)0;
            #pragma unroll
            for (int ni = 0; ni < 8; ni++) {
                int col = col0 + warp_n * 64 + ni * 8 + l4 * 2;
                float v0 = acc[mi][ni][half * 2 + 0];
                float v1 = acc[mi][ni][half * 2 + 1];
                if (bias) { v0 += bias[col]; v1 += bias[col + 1]; }
                if (gelu) { v0 = gelu_exact(v0); v1 = gelu_exact(v1); }
                if (res)  { float2 rr = *(const float2*)&rrow[col]; v0 += rr.x; v1 += rr.y; }
                *(float2*)&crow[col] = make_float2(v0, v1);
            }
        }
    }
}

// ---------------- launch ----------------------------------------------------
extern "C" void kernel_launch(void* const* d_in, const int* in_sizes, int n_in,
                              void* d_out, int out_size) {
    const float* x      = (const float*)d_in[0];
    const float* ln1_g  = (const float*)d_in[1];
    const float* ln1_b  = (const float*)d_in[2];
    const float* qkv_w  = (const float*)d_in[3];
    const float* qkv_b  = (const float*)d_in[4];
    const float* proj_w = (const float*)d_in[5];
    const float* proj_b = (const float*)d_in[6];
    const float* ln2_g  = (const float*)d_in[7];
    const float* ln2_b  = (const float*)d_in[8];
    const float* fc1_w  = (const float*)d_in[9];
    const float* fc1_b  = (const float*)d_in[10];
    const float* fc2_w  = (const float*)d_in[11];
    const float* fc2_b  = (const float*)d_in[12];
    float* out = (float*)d_out;

    float *h, *qkv, *attn, *x1, *h2;
    cudaGetSymbolAddress((void**)&h,    g_h);
    cudaGetSymbolAddress((void**)&qkv,  g_qkv);
    cudaGetSymbolAddress((void**)&attn, g_attn);
    cudaGetSymbolAddress((void**)&x1,   g_x1);
    cudaGetSymbolAddress((void**)&h2,   g_h2);

    cudaFuncSetAttribute(flash_kernel,
                         cudaFuncAttributeMaxDynamicSharedMemorySize, FA_SMEM_BYTES);
    cudaFuncSetAttribute(gemm_tf32_kernel,
                         cudaFuncAttributeMaxDynamicSharedMemorySize, GM_SMEM_BYTES);

    // 1. LN1
    ln_kernel<<<TOKENS / 8, 256>>>(x, ln1_g, ln1_b, h);

    // 2. QKV = h @ qkv_w^T + qkv_b      [8192 x 2304], K=768
    gemm_tf32_kernel<<<dim3(3 * DIM / 128, TOKENS / 128), 256, GM_SMEM_BYTES>>>(
        h, DIM, qkv_w, DIM, qkv, 3 * DIM, qkv_b, nullptr, DIM, 0);

    // 3-5. fused flash attention -> attn [token][DIM]
    flash_kernel<<<dim3(SEQ / FA_BR, BATCH * NH), 256, FA_SMEM_BYTES>>>(qkv, attn);

    // 6. x1 = x + attn @ proj_w^T + proj_b
    gemm_tf32_kernel<<<dim3(DIM / 128, TOKENS / 128), 256, GM_SMEM_BYTES>>>(
        attn, DIM, proj_w, DIM, x1, DIM, proj_b, x, DIM, 0);

    // 7. LN2
    ln_kernel<<<TOKENS / 8, 256>>>(x1, ln2_g, ln2_b, h);

    // 8. h2 = gelu(h @ fc1_w^T + fc1_b)   [8192 x 3072], K=768
    gemm_tf32_kernel<<<dim3(HIDDEN / 128, TOKENS / 128), 256, GM_SMEM_BYTES>>>(
        h, DIM, fc1_w, DIM, h2, HIDDEN, fc1_b, nullptr, DIM, 1);

    // 9. out = x1 + h2 @ fc2_w^T + fc2_b  [8192 x 768], K=3072
    gemm_tf32_kernel<<<dim3(DIM / 128, TOKENS / 128), 256, GM_SMEM_BYTES>>>(
        h2, HIDDEN, fc2_w, HIDDEN, out, DIM, fc2_b, x1, HIDDEN, 0);
}